// round 16
// baseline (speedup 1.0000x reference)
#include <cuda_runtime.h>
#include <cuda_bf16.h>
#include <cuda_fp16.h>
#include <cstdint>

#define D1 4096
#define D2 4096
#define KTOT 4096
#define ALPHA 300.0f

// ---- main GEMM tiling (R10 configuration) ----
#define BM 256
#define BN 128
#define BK 64
#define STAGES 4
#define RSB 144                          // 128B row + 16B pad (16B-aligned)
#define A_OFF 0
#define B_OFF (BM * RSB)                 // 36864
#define STG_BYTES ((BM + BN) * RSB)      // 55296
#define SMEM_MAIN (STAGES * STG_BYTES)   // 221184
#define NCH (KTOT / BK)                  // 64

// ---- wsplit GEMM ----
#define KUV 208                          // 2*nc=200 padded to mult of 16
#define RS2 432                          // 416B data + 16B pad; 16B-aligned
#define NSEG 26                          // 208 bf16 = 416 B = 26 x 16B segs
#define WS_SMEM (2 * 128 * RS2)          // 110592

// ---- combo prep ----
#define UV_BLOCKS 8192                   // 2 x 4096
#define XC_BLOCKS 2048

// ---------------- device globals (scratch) -----------------------------------
__device__ __nv_bfloat16 g_Ub[D1 * KUV];
__device__ __nv_bfloat16 g_Vb[D2 * KUV];
__device__ __half g_Wc[(size_t)D2 * D1];
__device__ __half g_X1[(size_t)8192 * D1];

// ---------------- PTX helpers (portable, sm_80-era) ---------------------------
__device__ __forceinline__ uint32_t smem_u32(const void* p) {
    uint32_t a;
    asm("{ .reg .u64 t; cvta.to.shared.u64 t, %1; cvt.u32.u64 %0, t; }" : "=r"(a) : "l"(p));
    return a;
}
__device__ __forceinline__ void cpa16(uint32_t d, const void* s) {
    asm volatile("cp.async.cg.shared.global [%0], [%1], 16;"
                 :: "r"(d), "l"(__cvta_generic_to_global(s)) : "memory");
}
__device__ __forceinline__ void ldsm4(uint32_t* r, uint32_t addr) {
    asm volatile("ldmatrix.sync.aligned.m8n8.x4.shared.b16 {%0,%1,%2,%3}, [%4];"
                 : "=r"(r[0]), "=r"(r[1]), "=r"(r[2]), "=r"(r[3]) : "r"(addr));
}
__device__ __forceinline__ void mma_f16(float* c, const uint32_t* a, const uint32_t* b) {
    asm volatile(
        "mma.sync.aligned.m16n8k16.row.col.f32.f16.f16.f32 "
        "{%0,%1,%2,%3}, {%4,%5,%6,%7}, {%8,%9}, {%0,%1,%2,%3};"
        : "+f"(c[0]), "+f"(c[1]), "+f"(c[2]), "+f"(c[3])
        : "r"(a[0]), "r"(a[1]), "r"(a[2]), "r"(a[3]), "r"(b[0]), "r"(b[1]));
}
__device__ __forceinline__ void mma_bf16(float* c, const uint32_t* a, const uint32_t* b) {
    asm volatile(
        "mma.sync.aligned.m16n8k16.row.col.f32.bf16.bf16.f32 "
        "{%0,%1,%2,%3}, {%4,%5,%6,%7}, {%8,%9}, {%0,%1,%2,%3};"
        : "+f"(c[0]), "+f"(c[1]), "+f"(c[2]), "+f"(c[3])
        : "r"(a[0]), "r"(a[1]), "r"(a[2]), "r"(a[3]), "r"(b[0]), "r"(b[1]));
}

// ---------------- combo prep: build U,V (+E decode) AND x -> fp16 --------------
__global__ void prep1_kernel(const float* __restrict__ c,
                             const unsigned int* __restrict__ ew,
                             int nc, float scale,
                             const float* __restrict__ x,
                             __half* __restrict__ X1, size_t n4) {
    const int j = threadIdx.x;

    if (blockIdx.x >= UV_BLOCKS) {
        // ---- xcvt part (DRAM-bound grid-stride) ----
        const float4* s4 = (const float4*)x;
        const size_t stride = (size_t)XC_BLOCKS * 128;
        for (size_t i = (size_t)(blockIdx.x - UV_BLOCKS) * 128 + j; i < n4; i += stride) {
            float4 v = s4[i];
            __half2 a = __halves2half2(__float2half_rn(v.x), __float2half_rn(v.y));
            __half2 b = __halves2half2(__float2half_rn(v.z), __float2half_rn(v.w));
            ((uint2*)X1)[i] = make_uint2(*(uint32_t*)&a, *(uint32_t*)&b);
        }
        return;
    }

    // ---- build U/V part ----
    const int k   = blockIdx.x & (D1 - 1);
    const bool isV = (blockIdx.x >= D1);
    unsigned int myw = (j < nc) ? ew[2 * j + 1] : 0u;
    bool is64 = (__syncthreads_or((int)(myw != 0u)) == 0);
    __nv_bfloat16* dst = (isV ? g_Vb : g_Ub) + (size_t)k * KUV;
    if (j < nc) {
        int f;
        if (is64) f = (int)(isV ? ew[4 * (nc + j)] : ew[4 * j]);
        else      f = (int)(isV ? ew[nc + j]       : ew[j]);
        int p = (f * k) & (D1 - 1);
        float ang = (float)p * (6.2831853071795864769f / (float)D1);
        float sn, cs;
        sincosf(ang, &sn, &cs);
        if (isV) {
            dst[2 * j]     = __float2bfloat16(cs);
            dst[2 * j + 1] = __float2bfloat16(sn);
        } else {
            float a = c[j] * scale;
            dst[2 * j]     = __float2bfloat16(a * cs);
            dst[2 * j + 1] = __float2bfloat16(-a * sn);
        }
    } else if (2 * j < KUV) {
        dst[2 * j]     = __float2bfloat16(0.f);
        dst[2 * j + 1] = __float2bfloat16(0.f);
    }
}

// ---------------- wsplit: Wc[l,k] = sum_t V[l,t]U[k,t] + W[l,k] -> fp16 --------
// W prefetched into registers BEFORE the MMA loop: the 16 float2 DRAM loads
// issue with MLP=16 and are consumed ~2000 cycles later in the epilogue, fully
// hidden behind the 13 MMA k-steps.
__global__ void __launch_bounds__(256, 1)
wsplit_kernel(const float* __restrict__ W, __half* __restrict__ Wc) {
    extern __shared__ __align__(128) char smem[];
    const uint32_t sb = smem_u32(smem);
    const uint32_t sbV = sb, sbU = sb + 128 * RS2;
    const int tid = threadIdx.x, lane = tid & 31, wid = tid >> 5;
    const int wm = wid & 3, wn = wid >> 2;
    const int l0 = blockIdx.y * 128, k0 = blockIdx.x * 128;

    // load V/U tiles: 128 rows x NSEG(=26) segs of 16B each (416 B = 208 bf16)
#pragma unroll
    for (int it = 0; it < (128 * NSEG + 255) / 256; ++it) {
        int idx = it * 256 + tid;
        if (idx < 128 * NSEG) {
            int row = idx / NSEG, seg = idx % NSEG;
            uint32_t so = (uint32_t)(row * RS2 + seg * 16);
            cpa16(sbV + so, g_Vb + (size_t)(l0 + row) * KUV + seg * 8);
            cpa16(sbU + so, g_Ub + (size_t)(k0 + row) * KUV + seg * 8);
        }
    }
    asm volatile("cp.async.commit_group;" ::: "memory");

    const int crow = l0 + wm * 32 + (lane >> 2);
    const int ccol = k0 + wn * 64 + 2 * (lane & 3);

    // prefetch W (consumed only in the epilogue)
    float2 wre[2][8][2];
#pragma unroll
    for (int i = 0; i < 2; ++i)
#pragma unroll
        for (int j = 0; j < 8; ++j)
#pragma unroll
            for (int h = 0; h < 2; ++h) {
                int r = crow + i * 16 + h * 8;
                wre[i][j][h] = __ldg((const float2*)(W + (size_t)r * D1 + ccol + j * 8));
            }

    asm volatile("cp.async.wait_group 0;" ::: "memory");
    __syncthreads();

    const int a_row = (lane & 7) + ((lane >> 3) & 1) * 8;
    const int a_col = ((lane >> 4) & 1) * 8;
    const uint32_t a_off = (uint32_t)((wm * 32 + a_row) * RS2 + a_col * 2);
    const int b_row = (lane & 7) + ((lane >> 4) & 1) * 8;
    const int b_col = ((lane >> 3) & 1) * 8;
    const uint32_t b_off = (uint32_t)((wn * 64 + b_row) * RS2 + b_col * 2);

    float acc[2][8][4];
#pragma unroll
    for (int i = 0; i < 2; ++i)
#pragma unroll
        for (int j = 0; j < 8; ++j)
#pragma unroll
            for (int q = 0; q < 4; ++q) acc[i][j][q] = 0.f;

#pragma unroll
    for (int ks = 0; ks < KUV / 16; ++ks) {      // 13 k-steps
        uint32_t a[2][4], b[8][2];
#pragma unroll
        for (int i = 0; i < 2; ++i)
            ldsm4(a[i], sbV + a_off + i * (16 * RS2) + ks * 32);
#pragma unroll
        for (int j = 0; j < 4; ++j) {
            uint32_t t4[4];
            ldsm4(t4, sbU + b_off + j * (16 * RS2) + ks * 32);
            b[2*j][0] = t4[0]; b[2*j][1] = t4[1];
            b[2*j+1][0] = t4[2]; b[2*j+1][1] = t4[3];
        }
#pragma unroll
        for (int i = 0; i < 2; ++i)
#pragma unroll
            for (int j = 0; j < 8; ++j)
                mma_bf16(acc[i][j], a[i], b[j]);
    }

#pragma unroll
    for (int i = 0; i < 2; ++i) {
#pragma unroll
        for (int j = 0; j < 8; ++j) {
#pragma unroll
            for (int h = 0; h < 2; ++h) {
                int r = crow + i * 16 + h * 8;
                size_t o = (size_t)r * D1 + ccol + j * 8;
                *(__half2*)(Wc + o) = __halves2half2(
                    __float2half_rn(acc[i][j][2*h]   + wre[i][j][h].x),
                    __float2half_rn(acc[i][j][2*h+1] + wre[i][j][h].y));
            }
        }
    }
}

// ---------------- main GEMM: out = X1 Wc^T + b  (fp16, mma.sync) --------------
// R10 configuration (verbatim): CTA 256x128x64, 4-stage cp.async, 8 warps
// (4x2), warp tile 64x64, fragment double-buffering across k16 steps and
// chunk boundaries, per-chunk wait_group(1) + __syncthreads.
__global__ void __launch_bounds__(256, 1)
gemm_mma_kernel(const __half* __restrict__ X1,
                const __half* __restrict__ Wc,
                const float* __restrict__ bias,
                float* __restrict__ out) {
    extern __shared__ __align__(128) char smem[];
    const uint32_t sb = smem_u32(smem);
    const int tid  = threadIdx.x;
    const int lane = tid & 31;
    const int wid  = tid >> 5;
    const int wm   = wid & 3;
    const int wn   = wid >> 2;
    const int m0   = blockIdx.y * BM;
    const int n0   = blockIdx.x * BN;

    auto load_chunk = [&](int stg, int chunk) {
        const uint32_t base = sb + stg * STG_BYTES;
        const int kc = chunk * BK;
#pragma unroll
        for (int it = 0; it < 8; ++it) {         // A: 256 rows x 8 segs of 16B
            int idx = it * 256 + tid;
            int row = idx >> 3, seg = idx & 7;
            uint32_t so = (uint32_t)(row * RSB + seg * 16);
            cpa16(base + A_OFF + so, X1 + (size_t)(m0 + row) * KTOT + kc + seg * 8);
        }
#pragma unroll
        for (int it = 0; it < 4; ++it) {         // B: 128 rows x 8 segs
            int idx = it * 256 + tid;
            int row = idx >> 3, seg = idx & 7;
            uint32_t so = (uint32_t)(row * RSB + seg * 16);
            cpa16(base + B_OFF + so, Wc + (size_t)(n0 + row) * KTOT + kc + seg * 8);
        }
    };

    const int a_row = (lane & 7) + ((lane >> 3) & 1) * 8;
    const int a_col = ((lane >> 4) & 1) * 8;
    const uint32_t a_off = (uint32_t)((wm * 64 + a_row) * RSB + a_col * 2);
    const int b_row = (lane & 7) + ((lane >> 4) & 1) * 8;
    const int b_col = ((lane >> 3) & 1) * 8;
    const uint32_t b_off = (uint32_t)((wn * 64 + b_row) * RSB + b_col * 2);

    uint32_t af[2][4][4], bf[2][8][2];
    auto ldfrag = [&](int buf, uint32_t st, int kk) {
#pragma unroll
        for (int i = 0; i < 4; ++i)
            ldsm4(af[buf][i], st + A_OFF + a_off + i * (16 * RSB) + kk * 32);
#pragma unroll
        for (int j = 0; j < 4; ++j) {
            uint32_t t4[4];
            ldsm4(t4, st + B_OFF + b_off + j * (16 * RSB) + kk * 32);
            bf[buf][2*j][0] = t4[0]; bf[buf][2*j][1] = t4[1];
            bf[buf][2*j+1][0] = t4[2]; bf[buf][2*j+1][1] = t4[3];
        }
    };

    float acc[4][8][4];
#pragma unroll
    for (int i = 0; i < 4; ++i)
#pragma unroll
        for (int j = 0; j < 8; ++j)
#pragma unroll
            for (int q = 0; q < 4; ++q) acc[i][j][q] = 0.f;

    // prologue: chunks 0..2 in flight; 0,1 resident after wait
#pragma unroll
    for (int s = 0; s < 3; ++s) {
        load_chunk(s, s);
        asm volatile("cp.async.commit_group;" ::: "memory");
    }
    asm volatile("cp.async.wait_group 1;" ::: "memory");
    __syncthreads();
    ldfrag(0, sb, 0);

    for (int it = 0; it < NCH; ++it) {
        const uint32_t st  = sb + (it & 3) * STG_BYTES;
        const uint32_t stn = sb + ((it + 1) & 3) * STG_BYTES;

        if (it + 3 < NCH) load_chunk((it + 3) & 3, it + 3);
        asm volatile("cp.async.commit_group;" ::: "memory");

#pragma unroll
        for (int kk = 0; kk < 4; ++kk) {
            const int cur = kk & 1;
            if (kk < 3)            ldfrag(cur ^ 1, st, kk + 1);
            else if (it + 1 < NCH) ldfrag(cur ^ 1, stn, 0);   // next chunk kk=0
#pragma unroll
            for (int i = 0; i < 4; ++i)
#pragma unroll
                for (int j = 0; j < 8; ++j)
                    mma_f16(acc[i][j], af[cur][i], bf[cur][j]);
        }
        asm volatile("cp.async.wait_group 1;" ::: "memory");
        __syncthreads();
    }

    // epilogue
    const int col_base = n0 + wn * 64 + 2 * (lane & 3);
    float2 bj[8];
#pragma unroll
    for (int j = 0; j < 8; ++j) {
        bj[j].x = __ldg(bias + col_base + j * 8);
        bj[j].y = __ldg(bias + col_base + j * 8 + 1);
    }
    const int row_base = m0 + wm * 64 + (lane >> 2);
#pragma unroll
    for (int i = 0; i < 4; ++i) {
#pragma unroll
        for (int j = 0; j < 8; ++j) {
            size_t o0 = (size_t)(row_base + i * 16) * D2 + col_base + j * 8;
            size_t o1 = o0 + 8 * D2;
            *(float2*)(out + o0) = make_float2(acc[i][j][0] + bj[j].x, acc[i][j][1] + bj[j].y);
            *(float2*)(out + o1) = make_float2(acc[i][j][2] + bj[j].x, acc[i][j][3] + bj[j].y);
        }
    }
}

// -----------------------------------------------------------------------------
extern "C" void kernel_launch(void* const* d_in, const int* in_sizes, int n_in,
                              void* d_out, int out_size) {
    const float*        x = (const float*)d_in[0];
    const float*        c = (const float*)d_in[1];
    const unsigned int* E = (const unsigned int*)d_in[2];
    const float*        W = (const float*)d_in[3];
    const float*        b = (const float*)d_in[4];
    float*            out = (float*)d_out;

    int nc = in_sizes[1];
    int M  = in_sizes[0] / D1;      // 8192

    __half *Wc, *X1;
    cudaGetSymbolAddress((void**)&Wc, g_Wc);
    cudaGetSymbolAddress((void**)&X1, g_X1);

    float scale = ALPHA / ((float)D1 * (float)D2);
    size_t n4 = (size_t)M * D1 / 4;

    prep1_kernel<<<UV_BLOCKS + XC_BLOCKS, 128>>>(c, E, nc, scale, x, X1, n4);

    cudaFuncSetAttribute(wsplit_kernel,
                         cudaFuncAttributeMaxDynamicSharedMemorySize, WS_SMEM);
    wsplit_kernel<<<dim3(D1 / 128, D2 / 128), 256, WS_SMEM>>>(W, Wc);

    cudaFuncSetAttribute(gemm_mma_kernel,
                         cudaFuncAttributeMaxDynamicSharedMemorySize, SMEM_MAIN);
    gemm_mma_kernel<<<dim3(D2 / BN, M / BM), 256, SMEM_MAIN>>>(
        X1, Wc, b, out);
}

// round 17
// speedup vs baseline: 1.0175x; 1.0175x over previous
#include <cuda_runtime.h>
#include <cuda_bf16.h>
#include <cuda_fp16.h>
#include <cstdint>

#define D1 4096
#define D2 4096
#define KTOT 4096
#define ALPHA 300.0f

// ---- main GEMM tiling (R10 configuration) ----
#define BM 256
#define BN 128
#define BK 64
#define STAGES 4
#define RSB 144                          // 128B row + 16B pad (16B-aligned)
#define A_OFF 0
#define B_OFF (BM * RSB)                 // 36864
#define STG_BYTES ((BM + BN) * RSB)      // 55296
#define SMEM_MAIN (STAGES * STG_BYTES)   // 221184
#define NCH (KTOT / BK)                  // 64

// ---- wsplit GEMM: tile 128(l) x 64(k), 2 CTAs/SM ----
#define KUV 208                          // 2*nc=200 padded to mult of 16
#define RS2 432                          // 416B data + 16B pad; 16B-aligned
#define NSEG 26                          // 208 bf16 = 416 B = 26 x 16B segs
#define WS_LM 128
#define WS_KM 64
#define WS_SMEM ((WS_LM + WS_KM) * RS2)  // 82944 -> 2 CTAs/SM

// ---- combo prep ----
#define UV_BLOCKS 8192                   // 2 x 4096
#define XC_BLOCKS 1024

// ---------------- device globals (scratch) -----------------------------------
__device__ __nv_bfloat16 g_Ub[D1 * KUV];
__device__ __nv_bfloat16 g_Vb[D2 * KUV];
__device__ __half g_Wc[(size_t)D2 * D1];
__device__ __half g_X1[(size_t)8192 * D1];

// ---------------- PTX helpers (portable, sm_80-era) ---------------------------
__device__ __forceinline__ uint32_t smem_u32(const void* p) {
    uint32_t a;
    asm("{ .reg .u64 t; cvta.to.shared.u64 t, %1; cvt.u32.u64 %0, t; }" : "=r"(a) : "l"(p));
    return a;
}
__device__ __forceinline__ void cpa16(uint32_t d, const void* s) {
    asm volatile("cp.async.cg.shared.global [%0], [%1], 16;"
                 :: "r"(d), "l"(__cvta_generic_to_global(s)) : "memory");
}
__device__ __forceinline__ void ldsm4(uint32_t* r, uint32_t addr) {
    asm volatile("ldmatrix.sync.aligned.m8n8.x4.shared.b16 {%0,%1,%2,%3}, [%4];"
                 : "=r"(r[0]), "=r"(r[1]), "=r"(r[2]), "=r"(r[3]) : "r"(addr));
}
__device__ __forceinline__ void mma_f16(float* c, const uint32_t* a, const uint32_t* b) {
    asm volatile(
        "mma.sync.aligned.m16n8k16.row.col.f32.f16.f16.f32 "
        "{%0,%1,%2,%3}, {%4,%5,%6,%7}, {%8,%9}, {%0,%1,%2,%3};"
        : "+f"(c[0]), "+f"(c[1]), "+f"(c[2]), "+f"(c[3])
        : "r"(a[0]), "r"(a[1]), "r"(a[2]), "r"(a[3]), "r"(b[0]), "r"(b[1]));
}
__device__ __forceinline__ void mma_bf16(float* c, const uint32_t* a, const uint32_t* b) {
    asm volatile(
        "mma.sync.aligned.m16n8k16.row.col.f32.bf16.bf16.f32 "
        "{%0,%1,%2,%3}, {%4,%5,%6,%7}, {%8,%9}, {%0,%1,%2,%3};"
        : "+f"(c[0]), "+f"(c[1]), "+f"(c[2]), "+f"(c[3])
        : "r"(a[0]), "r"(a[1]), "r"(a[2]), "r"(a[3]), "r"(b[0]), "r"(b[1]));
}

// ---------------- combo prep: build U,V (+E decode) AND x -> fp16 --------------
__global__ void prep1_kernel(const float* __restrict__ c,
                             const unsigned int* __restrict__ ew,
                             int nc, float scale,
                             const float* __restrict__ x,
                             __half* __restrict__ X1, size_t n4) {
    const int j = threadIdx.x;

    if (blockIdx.x >= UV_BLOCKS) {
        // ---- xcvt part (DRAM-bound grid-stride) ----
        const float4* s4 = (const float4*)x;
        const size_t stride = (size_t)XC_BLOCKS * 128;
        for (size_t i = (size_t)(blockIdx.x - UV_BLOCKS) * 128 + j; i < n4; i += stride) {
            float4 v = s4[i];
            __half2 a = __halves2half2(__float2half_rn(v.x), __float2half_rn(v.y));
            __half2 b = __halves2half2(__float2half_rn(v.z), __float2half_rn(v.w));
            ((uint2*)X1)[i] = make_uint2(*(uint32_t*)&a, *(uint32_t*)&b);
        }
        return;
    }

    // ---- build U/V part ----
    const int k   = blockIdx.x & (D1 - 1);
    const bool isV = (blockIdx.x >= D1);
    unsigned int myw = (j < nc) ? ew[2 * j + 1] : 0u;
    bool is64 = (__syncthreads_or((int)(myw != 0u)) == 0);
    __nv_bfloat16* dst = (isV ? g_Vb : g_Ub) + (size_t)k * KUV;
    if (j < nc) {
        int f;
        if (is64) f = (int)(isV ? ew[4 * (nc + j)] : ew[4 * j]);
        else      f = (int)(isV ? ew[nc + j]       : ew[j]);
        int p = (f * k) & (D1 - 1);
        float ang = (float)p * (6.2831853071795864769f / (float)D1);
        float sn, cs;
        sincosf(ang, &sn, &cs);
        if (isV) {
            dst[2 * j]     = __float2bfloat16(cs);
            dst[2 * j + 1] = __float2bfloat16(sn);
        } else {
            float a = c[j] * scale;
            dst[2 * j]     = __float2bfloat16(a * cs);
            dst[2 * j + 1] = __float2bfloat16(-a * sn);
        }
    } else if (2 * j < KUV) {
        dst[2 * j]     = __float2bfloat16(0.f);
        dst[2 * j + 1] = __float2bfloat16(0.f);
    }
}

// ---------------- wsplit: Wc[l,k] = sum_t V[l,t]U[k,t] + W[l,k] -> fp16 --------
// Tile 128(l) x 64(k), 83 KB smem -> 2 CTAs/SM; co-resident CTA hides the
// load-wait and epilogue DRAM latency. 8 warps in 4x2 -> warp tile 32x32.
__global__ void __launch_bounds__(256, 2)
wsplit_kernel(const float* __restrict__ W, __half* __restrict__ Wc) {
    extern __shared__ __align__(128) char smem[];
    const uint32_t sb = smem_u32(smem);
    const uint32_t sbV = sb, sbU = sb + WS_LM * RS2;
    const int tid = threadIdx.x, lane = tid & 31, wid = tid >> 5;
    const int wm = wid & 3, wn = wid >> 2;
    const int l0 = blockIdx.y * WS_LM, k0 = blockIdx.x * WS_KM;

    // load V tile: 128 rows x 26 segs = 3328 -> 13 exact iters
#pragma unroll
    for (int it = 0; it < 13; ++it) {
        int idx = it * 256 + tid;
        int row = idx / NSEG, seg = idx % NSEG;
        uint32_t so = (uint32_t)(row * RS2 + seg * 16);
        cpa16(sbV + so, g_Vb + (size_t)(l0 + row) * KUV + seg * 8);
    }
    // load U tile: 64 rows x 26 segs = 1664 -> 7 iters w/ bound
#pragma unroll
    for (int it = 0; it < 7; ++it) {
        int idx = it * 256 + tid;
        if (idx < WS_KM * NSEG) {
            int row = idx / NSEG, seg = idx % NSEG;
            uint32_t so = (uint32_t)(row * RS2 + seg * 16);
            cpa16(sbU + so, g_Ub + (size_t)(k0 + row) * KUV + seg * 8);
        }
    }
    asm volatile("cp.async.commit_group;" ::: "memory");
    asm volatile("cp.async.wait_group 0;" ::: "memory");
    __syncthreads();

    const int a_row = (lane & 7) + ((lane >> 3) & 1) * 8;
    const int a_col = ((lane >> 4) & 1) * 8;
    const uint32_t a_off = (uint32_t)((wm * 32 + a_row) * RS2 + a_col * 2);
    const int b_row = (lane & 7) + ((lane >> 4) & 1) * 8;
    const int b_col = ((lane >> 3) & 1) * 8;
    const uint32_t b_off = (uint32_t)((wn * 32 + b_row) * RS2 + b_col * 2);

    float acc[2][4][4];
#pragma unroll
    for (int i = 0; i < 2; ++i)
#pragma unroll
        for (int j = 0; j < 4; ++j)
#pragma unroll
            for (int q = 0; q < 4; ++q) acc[i][j][q] = 0.f;

#pragma unroll
    for (int ks = 0; ks < KUV / 16; ++ks) {      // 13 k-steps
        uint32_t a[2][4], b[4][2];
#pragma unroll
        for (int i = 0; i < 2; ++i)
            ldsm4(a[i], sbV + a_off + i * (16 * RS2) + ks * 32);
#pragma unroll
        for (int jj = 0; jj < 2; ++jj) {
            uint32_t t4[4];
            ldsm4(t4, sbU + b_off + jj * (16 * RS2) + ks * 32);
            b[2*jj][0] = t4[0]; b[2*jj][1] = t4[1];
            b[2*jj+1][0] = t4[2]; b[2*jj+1][1] = t4[3];
        }
#pragma unroll
        for (int i = 0; i < 2; ++i)
#pragma unroll
            for (int j = 0; j < 4; ++j)
                mma_bf16(acc[i][j], a[i], b[j]);
    }

    const int crow = l0 + wm * 32 + (lane >> 2);
    const int ccol = k0 + wn * 32 + 2 * (lane & 3);
#pragma unroll
    for (int i = 0; i < 2; ++i) {
#pragma unroll
        for (int j = 0; j < 4; ++j) {
#pragma unroll
            for (int h = 0; h < 2; ++h) {
                int r = crow + i * 16 + h * 8;
                size_t o = (size_t)r * D1 + ccol + j * 8;
                float2 w = *(const float2*)(W + o);
                *(__half2*)(Wc + o) = __halves2half2(
                    __float2half_rn(acc[i][j][2*h]   + w.x),
                    __float2half_rn(acc[i][j][2*h+1] + w.y));
            }
        }
    }
}

// ---------------- main GEMM: out = X1 Wc^T + b  (fp16, mma.sync) --------------
// R10 configuration (verbatim): CTA 256x128x64, 4-stage cp.async, 8 warps
// (4x2), warp tile 64x64, fragment double-buffering across k16 steps and
// chunk boundaries, per-chunk wait_group(1) + __syncthreads.
__global__ void __launch_bounds__(256, 1)
gemm_mma_kernel(const __half* __restrict__ X1,
                const __half* __restrict__ Wc,
                const float* __restrict__ bias,
                float* __restrict__ out) {
    extern __shared__ __align__(128) char smem[];
    const uint32_t sb = smem_u32(smem);
    const int tid  = threadIdx.x;
    const int lane = tid & 31;
    const int wid  = tid >> 5;
    const int wm   = wid & 3;
    const int wn   = wid >> 2;
    const int m0   = blockIdx.y * BM;
    const int n0   = blockIdx.x * BN;

    auto load_chunk = [&](int stg, int chunk) {
        const uint32_t base = sb + stg * STG_BYTES;
        const int kc = chunk * BK;
#pragma unroll
        for (int it = 0; it < 8; ++it) {         // A: 256 rows x 8 segs of 16B
            int idx = it * 256 + tid;
            int row = idx >> 3, seg = idx & 7;
            uint32_t so = (uint32_t)(row * RSB + seg * 16);
            cpa16(base + A_OFF + so, X1 + (size_t)(m0 + row) * KTOT + kc + seg * 8);
        }
#pragma unroll
        for (int it = 0; it < 4; ++it) {         // B: 128 rows x 8 segs
            int idx = it * 256 + tid;
            int row = idx >> 3, seg = idx & 7;
            uint32_t so = (uint32_t)(row * RSB + seg * 16);
            cpa16(base + B_OFF + so, Wc + (size_t)(n0 + row) * KTOT + kc + seg * 8);
        }
    };

    const int a_row = (lane & 7) + ((lane >> 3) & 1) * 8;
    const int a_col = ((lane >> 4) & 1) * 8;
    const uint32_t a_off = (uint32_t)((wm * 64 + a_row) * RSB + a_col * 2);
    const int b_row = (lane & 7) + ((lane >> 4) & 1) * 8;
    const int b_col = ((lane >> 3) & 1) * 8;
    const uint32_t b_off = (uint32_t)((wn * 64 + b_row) * RSB + b_col * 2);

    uint32_t af[2][4][4], bf[2][8][2];
    auto ldfrag = [&](int buf, uint32_t st, int kk) {
#pragma unroll
        for (int i = 0; i < 4; ++i)
            ldsm4(af[buf][i], st + A_OFF + a_off + i * (16 * RSB) + kk * 32);
#pragma unroll
        for (int j = 0; j < 4; ++j) {
            uint32_t t4[4];
            ldsm4(t4, st + B_OFF + b_off + j * (16 * RSB) + kk * 32);
            bf[buf][2*j][0] = t4[0]; bf[buf][2*j][1] = t4[1];
            bf[buf][2*j+1][0] = t4[2]; bf[buf][2*j+1][1] = t4[3];
        }
    };

    float acc[4][8][4];
#pragma unroll
    for (int i = 0; i < 4; ++i)
#pragma unroll
        for (int j = 0; j < 8; ++j)
#pragma unroll
            for (int q = 0; q < 4; ++q) acc[i][j][q] = 0.f;

    // prologue: chunks 0..2 in flight; 0,1 resident after wait
#pragma unroll
    for (int s = 0; s < 3; ++s) {
        load_chunk(s, s);
        asm volatile("cp.async.commit_group;" ::: "memory");
    }
    asm volatile("cp.async.wait_group 1;" ::: "memory");
    __syncthreads();
    ldfrag(0, sb, 0);

    for (int it = 0; it < NCH; ++it) {
        const uint32_t st  = sb + (it & 3) * STG_BYTES;
        const uint32_t stn = sb + ((it + 1) & 3) * STG_BYTES;

        if (it + 3 < NCH) load_chunk((it + 3) & 3, it + 3);
        asm volatile("cp.async.commit_group;" ::: "memory");

#pragma unroll
        for (int kk = 0; kk < 4; ++kk) {
            const int cur = kk & 1;
            if (kk < 3)            ldfrag(cur ^ 1, st, kk + 1);
            else if (it + 1 < NCH) ldfrag(cur ^ 1, stn, 0);   // next chunk kk=0
#pragma unroll
            for (int i = 0; i < 4; ++i)
#pragma unroll
                for (int j = 0; j < 8; ++j)
                    mma_f16(acc[i][j], af[cur][i], bf[cur][j]);
        }
        asm volatile("cp.async.wait_group 1;" ::: "memory");
        __syncthreads();
    }

    // epilogue
    const int col_base = n0 + wn * 64 + 2 * (lane & 3);
    float2 bj[8];
#pragma unroll
    for (int j = 0; j < 8; ++j) {
        bj[j].x = __ldg(bias + col_base + j * 8);
        bj[j].y = __ldg(bias + col_base + j * 8 + 1);
    }
    const int row_base = m0 + wm * 64 + (lane >> 2);
#pragma unroll
    for (int i = 0; i < 4; ++i) {
#pragma unroll
        for (int j = 0; j < 8; ++j) {
            size_t o0 = (size_t)(row_base + i * 16) * D2 + col_base + j * 8;
            size_t o1 = o0 + 8 * D2;
            *(float2*)(out + o0) = make_float2(acc[i][j][0] + bj[j].x, acc[i][j][1] + bj[j].y);
            *(float2*)(out + o1) = make_float2(acc[i][j][2] + bj[j].x, acc[i][j][3] + bj[j].y);
        }
    }
}

// -----------------------------------------------------------------------------
extern "C" void kernel_launch(void* const* d_in, const int* in_sizes, int n_in,
                              void* d_out, int out_size) {
    const float*        x = (const float*)d_in[0];
    const float*        c = (const float*)d_in[1];
    const unsigned int* E = (const unsigned int*)d_in[2];
    const float*        W = (const float*)d_in[3];
    const float*        b = (const float*)d_in[4];
    float*            out = (float*)d_out;

    int nc = in_sizes[1];
    int M  = in_sizes[0] / D1;      // 8192

    __half *Wc, *X1;
    cudaGetSymbolAddress((void**)&Wc, g_Wc);
    cudaGetSymbolAddress((void**)&X1, g_X1);

    float scale = ALPHA / ((float)D1 * (float)D2);
    size_t n4 = (size_t)M * D1 / 4;

    prep1_kernel<<<UV_BLOCKS + XC_BLOCKS, 128>>>(c, E, nc, scale, x, X1, n4);

    cudaFuncSetAttribute(wsplit_kernel,
                         cudaFuncAttributeMaxDynamicSharedMemorySize, WS_SMEM);
    wsplit_kernel<<<dim3(D1 / WS_KM, D2 / WS_LM), 256, WS_SMEM>>>(W, Wc);

    cudaFuncSetAttribute(gemm_mma_kernel,
                         cudaFuncAttributeMaxDynamicSharedMemorySize, SMEM_MAIN);
    gemm_mma_kernel<<<dim3(D2 / BN, M / BM), 256, SMEM_MAIN>>>(
        X1, Wc, b, out);
}